// round 2
// baseline (speedup 1.0000x reference)
#include <cuda_runtime.h>

// Problem constants
#define Bb  8
#define NN  2048
#define DD  512
#define HH  8
#define DH  64
#define MTOT (Bb*NN)          // 16384 rows
#define NM1  (NN-1)           // 2047 mask cols

// Scratch (device globals: allocation-free rule)
__device__ float g_q[Bb*HH*NN*DH];    // [b][h][n][dh]
__device__ float g_k[Bb*HH*NN*DH];
__device__ float g_v[Bb*HH*NN*DH];
__device__ float g_ctx[Bb*NN*DD];     // [b][n][d]

// ---------------------------------------------------------------------------
// Tiled SIMT fp32 GEMM: C[M,N] = A[M,K] @ B[K,N] + bias[N]
// BM=BN=128, BK=16, 256 threads, 8x8 per thread (split 4+4 halves).
// MODE 0: plain store to C.
// MODE 1: QKV scatter epilogue into g_q/g_k/g_v with [b,h,n,dh] layout.
// Assumes M%128==0, N%128==0, K%16==0 (true here).
// ---------------------------------------------------------------------------
template<int MODE>
__global__ __launch_bounds__(256)
void gemm_kernel(const float* __restrict__ A, const float* __restrict__ B,
                 const float* __restrict__ bias, float* __restrict__ C,
                 int M, int N, int K)
{
    const int BM = 128, BN = 128, BK = 16;
    __shared__ float As[BK][BM];   // transposed A tile
    __shared__ float Bs[BK][BN];

    const int tid = threadIdx.x;
    const int tx = tid & 15;       // 0..15
    const int ty = tid >> 4;       // 0..15
    const int m0 = blockIdx.y * BM;
    const int n0 = blockIdx.x * BN;

    float acc[8][8];
#pragma unroll
    for (int i = 0; i < 8; i++)
#pragma unroll
        for (int j = 0; j < 8; j++) acc[i][j] = 0.0f;

    for (int kb = 0; kb < K; kb += BK) {
#pragma unroll
        for (int it = 0; it < 2; it++) {
            // A: 128 rows x 16 cols, transposed into As
            int ar = (tid >> 2) + it * 64;       // 0..127
            int ac = (tid & 3) << 2;             // 0,4,8,12
            float4 av = *(const float4*)(A + (long)(m0 + ar) * K + kb + ac);
            As[ac + 0][ar] = av.x;
            As[ac + 1][ar] = av.y;
            As[ac + 2][ar] = av.z;
            As[ac + 3][ar] = av.w;
            // B: 16 rows x 128 cols, natural layout
            int br = (tid >> 5) + it * 8;        // 0..15
            int bc = (tid & 31) << 2;            // 0..124
            *(float4*)&Bs[br][bc] = *(const float4*)(B + (long)(kb + br) * N + n0 + bc);
        }
        __syncthreads();

#pragma unroll
        for (int k = 0; k < BK; k++) {
            float ar[8], br[8];
            *(float4*)&ar[0] = *(const float4*)&As[k][ty * 4];
            *(float4*)&ar[4] = *(const float4*)&As[k][64 + ty * 4];
            *(float4*)&br[0] = *(const float4*)&Bs[k][tx * 4];
            *(float4*)&br[4] = *(const float4*)&Bs[k][64 + tx * 4];
#pragma unroll
            for (int i = 0; i < 8; i++)
#pragma unroll
                for (int j = 0; j < 8; j++)
                    acc[i][j] += ar[i] * br[j];
        }
        __syncthreads();
    }

    // Epilogue
#pragma unroll
    for (int hi = 0; hi < 2; hi++) {
#pragma unroll
        for (int i = 0; i < 4; i++) {
            int r = m0 + hi * 64 + ty * 4 + i;
#pragma unroll
            for (int hj = 0; hj < 2; hj++) {
#pragma unroll
                for (int j = 0; j < 4; j++) {
                    int c = n0 + hj * 64 + tx * 4 + j;
                    float v = acc[hi * 4 + i][hj * 4 + j] + bias[c];
                    if (MODE == 0) {
                        C[(long)r * N + c] = v;
                    } else {
                        // scatter into q/k/v [b][h][n][dh]
                        int t = c >> 9;          // 0=q 1=k 2=v (constant per block)
                        int d = c & 511;
                        int head = d >> 6;
                        int w = d & 63;
                        int b = r >> 11;
                        int n = r & 2047;
                        float* dst = (t == 0) ? g_q : (t == 1) ? g_k : g_v;
                        dst[(((long)(b * HH) + head) * NN + n) * DH + w] = v;
                    }
                }
            }
        }
    }
}

// ---------------------------------------------------------------------------
// Flash attention: one block per (b, h, q-tile of 64).
// 256 threads = 16x16; each thread owns a 4x4 block of S/P and of O.
// Online softmax state (m, l) replicated across the 16 lanes of a row group
// via width-16 shfl reductions. P staged through smem for the PV product.
// ---------------------------------------------------------------------------
__device__ __forceinline__ unsigned mask_valid(const unsigned* __restrict__ mr,
                                               int b, int n)
{
    return (n == 0) ? 1u : (mr[(long)b * NM1 + n - 1] != 0u ? 1u : 0u);
}

__global__ __launch_bounds__(256)
void attn_kernel(const unsigned* __restrict__ mraw)
{
    extern __shared__ float sm[];
    float* Qs = sm;                 // [64][64] d-major: Qs[d*64 + q]
    float* Ks = sm + 4096;          // [64][64] d-major: Ks[d*64 + kk]
    float* Vs = sm + 8192;          // [64][64] kk-major: Vs[kk*64 + d]
    float* Ss = sm + 12288;         // [64][68] P tile (padded stride)
    unsigned* km = (unsigned*)(sm + 12288 + 64 * 68);  // [64]

    const int tid = threadIdx.x;
    const int tx = tid & 15;
    const int ty = tid >> 4;
    const int b = blockIdx.z;
    const int h = blockIdx.y;
    const int q0 = blockIdx.x * 64;
    const float scale = 0.044194173824159216f;  // 512^-0.5

    const float* Qp = g_q + (((long)(b * HH) + h) * NN + q0) * DH;
    const float* Kbase = g_k + ((long)(b * HH) + h) * NN * DH;
    const float* Vbase = g_v + ((long)(b * HH) + h) * NN * DH;

    // Load Q tile transposed (once)
    for (int idx = tid; idx < 1024; idx += 256) {
        int q = idx >> 4;
        int c4 = (idx & 15) << 2;
        float4 v = *(const float4*)(Qp + q * DH + c4);
        Qs[(c4 + 0) * 64 + q] = v.x;
        Qs[(c4 + 1) * 64 + q] = v.y;
        Qs[(c4 + 2) * 64 + q] = v.z;
        Qs[(c4 + 3) * 64 + q] = v.w;
    }

    unsigned qm[4];
#pragma unroll
    for (int i = 0; i < 4; i++)
        qm[i] = mask_valid(mraw, b, q0 + ty * 4 + i);

    float o[4][4];
    float mrow[4], lrow[4];
#pragma unroll
    for (int i = 0; i < 4; i++) {
        mrow[i] = -1e30f;
        lrow[i] = 0.0f;
#pragma unroll
        for (int j = 0; j < 4; j++) o[i][j] = 0.0f;
    }

    for (int kt = 0; kt < NN / 64; kt++) {
        const int k0 = kt * 64;
        __syncthreads();  // protect Ks/Vs/Ss from prior-iter readers

        const float* Kp = Kbase + (long)k0 * DH;
        const float* Vp = Vbase + (long)k0 * DH;
        for (int idx = tid; idx < 1024; idx += 256) {
            int r = idx >> 4;
            int c4 = (idx & 15) << 2;
            float4 kv = *(const float4*)(Kp + r * DH + c4);
            Ks[(c4 + 0) * 64 + r] = kv.x;
            Ks[(c4 + 1) * 64 + r] = kv.y;
            Ks[(c4 + 2) * 64 + r] = kv.z;
            Ks[(c4 + 3) * 64 + r] = kv.w;
            *(float4*)(Vs + r * 64 + c4) = *(const float4*)(Vp + r * DH + c4);
        }
        if (tid < 64) km[tid] = mask_valid(mraw, b, k0 + tid);
        __syncthreads();

        // S = Q @ K^T (64x64), per-thread 4x4
        float s[4][4];
#pragma unroll
        for (int i = 0; i < 4; i++)
#pragma unroll
            for (int j = 0; j < 4; j++) s[i][j] = 0.0f;

        for (int d = 0; d < 64; d++) {
            float4 qv = *(const float4*)(Qs + d * 64 + ty * 4);
            float4 kv = *(const float4*)(Ks + d * 64 + tx * 4);
            float qa[4] = {qv.x, qv.y, qv.z, qv.w};
            float ka[4] = {kv.x, kv.y, kv.z, kv.w};
#pragma unroll
            for (int i = 0; i < 4; i++)
#pragma unroll
                for (int j = 0; j < 4; j++)
                    s[i][j] += qa[i] * ka[j];
        }

        unsigned kmr[4];
#pragma unroll
        for (int j = 0; j < 4; j++) kmr[j] = km[tx * 4 + j];

        // Masked online softmax; width-16 shfl reductions over the row group
#pragma unroll
        for (int i = 0; i < 4; i++) {
#pragma unroll
            for (int j = 0; j < 4; j++)
                s[i][j] = (qm[i] & kmr[j]) ? s[i][j] * scale : -1e9f;
            float mx = fmaxf(fmaxf(s[i][0], s[i][1]), fmaxf(s[i][2], s[i][3]));
#pragma unroll
            for (int off = 1; off < 16; off <<= 1)
                mx = fmaxf(mx, __shfl_xor_sync(0xffffffffu, mx, off, 16));
            float mn = fmaxf(mrow[i], mx);
            float alpha = __expf(mrow[i] - mn);
            float rs = 0.0f;
#pragma unroll
            for (int j = 0; j < 4; j++) {
                float p = __expf(s[i][j] - mn);
                s[i][j] = p;
                rs += p;
            }
#pragma unroll
            for (int off = 1; off < 16; off <<= 1)
                rs += __shfl_xor_sync(0xffffffffu, rs, off, 16);
            lrow[i] = lrow[i] * alpha + rs;
            mrow[i] = mn;
#pragma unroll
            for (int j = 0; j < 4; j++) o[i][j] *= alpha;
            int r = ty * 4 + i;
            *(float4*)(Ss + r * 68 + tx * 4) =
                make_float4(s[i][0], s[i][1], s[i][2], s[i][3]);
        }
        __syncthreads();

        // O += P @ V
        for (int kk = 0; kk < 64; kk += 4) {
            float4 p[4];
#pragma unroll
            for (int i = 0; i < 4; i++)
                p[i] = *(const float4*)(Ss + (ty * 4 + i) * 68 + kk);
            float4 v0 = *(const float4*)(Vs + (kk + 0) * 64 + tx * 4);
            float4 v1 = *(const float4*)(Vs + (kk + 1) * 64 + tx * 4);
            float4 v2 = *(const float4*)(Vs + (kk + 2) * 64 + tx * 4);
            float4 v3 = *(const float4*)(Vs + (kk + 3) * 64 + tx * 4);
#pragma unroll
            for (int i = 0; i < 4; i++) {
                o[i][0] += p[i].x * v0.x + p[i].y * v1.x + p[i].z * v2.x + p[i].w * v3.x;
                o[i][1] += p[i].x * v0.y + p[i].y * v1.y + p[i].z * v2.y + p[i].w * v3.y;
                o[i][2] += p[i].x * v0.z + p[i].y * v1.z + p[i].z * v2.z + p[i].w * v3.z;
                o[i][3] += p[i].x * v0.w + p[i].y * v1.w + p[i].z * v2.w + p[i].w * v3.w;
            }
        }
    }

    // Normalize and write context [b][n][d]
#pragma unroll
    for (int i = 0; i < 4; i++) {
        float inv = 1.0f / lrow[i];
        int q = q0 + ty * 4 + i;
        float4 ov = make_float4(o[i][0] * inv, o[i][1] * inv,
                                o[i][2] * inv, o[i][3] * inv);
        *(float4*)(g_ctx + ((long)(b * NN) + q) * DD + h * DH + tx * 4) = ov;
    }
}

// ---------------------------------------------------------------------------
// Launch
// ---------------------------------------------------------------------------
extern "C" void kernel_launch(void* const* d_in, const int* in_sizes, int n_in,
                              void* d_out, int out_size)
{
    const float*    x    = (const float*)d_in[0];
    const unsigned* mask = (const unsigned*)d_in[1];   // bool serialized as 4B (int32/f32): !=0 works for both
    const float*    Wqkv = (const float*)d_in[2];
    const float*    bqkv = (const float*)d_in[3];
    const float*    Wout = (const float*)d_in[4];
    const float*    bout = (const float*)d_in[5];
    float*          out  = (float*)d_out;

    const int ATTN_SMEM = (12288 + 64 * 68 + 64) * 4;  // 66816 B
    cudaFuncSetAttribute(attn_kernel,
                         cudaFuncAttributeMaxDynamicSharedMemorySize, ATTN_SMEM);

    // 1) QKV projection + scatter into [b,h,n,dh]
    dim3 g1(3 * DD / 128, MTOT / 128);   // (12, 128)
    gemm_kernel<1><<<g1, 256>>>(x, Wqkv, bqkv, nullptr, MTOT, 3 * DD, DD);

    // 2) Flash attention -> g_ctx
    dim3 ga(NN / 64, HH, Bb);            // (32, 8, 8) = 2048 blocks
    attn_kernel<<<ga, 256, ATTN_SMEM>>>(mask);

    // 3) Output projection
    void* ctxp = nullptr;
    cudaGetSymbolAddress(&ctxp, g_ctx);
    dim3 g3(DD / 128, MTOT / 128);       // (4, 128)
    gemm_kernel<0><<<g3, 256>>>((const float*)ctxp, Wout, bout, out,
                                MTOT, DD, DD);
}